// round 14
// baseline (speedup 1.0000x reference)
#include <cuda_runtime.h>
#include <cuda_fp16.h>
#include <cstdint>

#define Nn    1024
#define NPp   1025
#define BHb   64
#define MXm   8192

typedef __half h16;

// ---------------- device scratch (all fp16) ----------------
__device__ h16 g_xf [(size_t)MXm * 512];
__device__ h16 g_wqf[(size_t)512 * 512];        // [n][k]
__device__ h16 g_wkvf[(size_t)1024 * 512];      // [n][k]
__device__ h16 g_wof[(size_t)512 * 512];        // [n][k]
__device__ h16 g_tf [(size_t)1088 * 64];        // pos table (padded)
__device__ h16 g_qf [(size_t)BHb * Nn * 64];    // scaled by 0.125*log2e
__device__ h16 g_kf [(size_t)BHb * Nn * 64];
__device__ h16 g_vtf[(size_t)BHb * 64 * Nn];    // v^T [bh][d][j]
__device__ h16 g_cf [(size_t)MXm * 512];        // ctx [b,n][h*d]
__device__ h16 g_Pg [(size_t)MXm * 8 * Nn];     // GATHERED pos: [bh*1024+i][j]

// ---------------- smem geometry ----------------
#define STRB  144
// GEMM kernels (qkv/out): A 128 rows + B 64 rows, 2 stages
#define B_OFF  18432u
#define BUFB   27648u
#define SMEM_G 55296
// pos: A 128 rows persistent + 2x B 64 rows
#define PB0      18432u
#define SMEM_POS 36864
// fused attention: Q 128 rows + 2x (K 64 + V 64 + P 128)
#define FQ      0u
#define FKV0    18432u
#define FKVSTR  36864u
#define FK      0u
#define FV      9216u
#define FP      18432u
#define SMEM_FA 92160

#define CP16(d, s)  asm volatile("cp.async.ca.shared.global [%0], [%1], 16;" :: "r"(d), "l"(s))
#define CP_COMMIT() asm volatile("cp.async.commit_group;" ::: "memory")
#define CP_WAIT(n)  asm volatile("cp.async.wait_group %0;" :: "n"(n) : "memory")

#define LDMX4(r0, r1, r2, r3, a) \
    asm volatile("ldmatrix.sync.aligned.m8n8.x4.shared.b16 {%0,%1,%2,%3}, [%4];" \
                 : "=r"(r0), "=r"(r1), "=r"(r2), "=r"(r3) : "r"(a))
#define LDS32(v, a) asm volatile("ld.shared.b32 %0, [%1];" : "=r"(v) : "r"(a))

static __device__ __forceinline__ uint32_t smem_u32(const void* p) {
    uint32_t a;
    asm("{ .reg .u64 t; cvta.to.shared.u64 t, %1; cvt.u32.u64 %0, t; }" : "=r"(a) : "l"(p));
    return a;
}
static __device__ __forceinline__ float ex2(float x) {
    float y;
    asm("ex2.approx.f32 %0, %1;" : "=f"(y) : "f"(x));
    return y;
}
static __device__ __forceinline__ void mma_f16(float* d, const uint32_t* a, const uint32_t* b) {
    asm volatile("mma.sync.aligned.m16n8k16.row.col.f32.f16.f16.f32 "
                 "{%0,%1,%2,%3}, {%4,%5,%6,%7}, {%8,%9}, {%0,%1,%2,%3};"
                 : "+f"(d[0]), "+f"(d[1]), "+f"(d[2]), "+f"(d[3])
                 : "r"(a[0]), "r"(a[1]), "r"(a[2]), "r"(a[3]), "r"(b[0]), "r"(b[1]));
}
static __device__ __forceinline__ uint32_t h2u(float a, float b) {
    __half2 h = __floats2half2_rn(a, b);
    return *(uint32_t*)&h;
}

template <int R, int T>
static __device__ __forceinline__ void stage_cp(uint32_t sdst, const h16* src, int lds, int t) {
    #pragma unroll
    for (int i = 0; i < R * 8 / T; i++) {
        int idx = t + i * T;
        int row = idx >> 3, ch = idx & 7;
        CP16(sdst + (uint32_t)row * STRB + (uint32_t)ch * 16,
             src + (size_t)row * lds + ch * 8);
    }
}

static __device__ __forceinline__ uint32_t lda_off(int lane) {
    return (uint32_t)(lane & 15) * STRB + (uint32_t)(lane & 16);
}
static __device__ __forceinline__ uint32_t ldb_off(int lane) {
    return (uint32_t)((lane & 7) + ((lane & 16) >> 1)) * STRB + (uint32_t)((lane & 8) << 1);
}

// single-term K=64 stage; warp tile 32x32
static __device__ __forceinline__ void compute_stage(uint32_t a_base, uint32_t b_base,
                                                     float acc[2][4][4]) {
    #pragma unroll
    for (int ks = 0; ks < 4; ks++) {
        uint32_t a[2][4], b[4][2];
        #pragma unroll
        for (int mi = 0; mi < 2; mi++) {
            uint32_t ad = a_base + (uint32_t)(mi * 16) * STRB + (uint32_t)(ks * 32);
            LDMX4(a[mi][0], a[mi][1], a[mi][2], a[mi][3], ad);
        }
        #pragma unroll
        for (int p = 0; p < 2; p++) {
            uint32_t bd = b_base + (uint32_t)(p * 16) * STRB + (uint32_t)(ks * 32);
            LDMX4(b[2 * p][0], b[2 * p][1], b[2 * p + 1][0], b[2 * p + 1][1], bd);
        }
        #pragma unroll
        for (int ni = 0; ni < 4; ni++)
            #pragma unroll
            for (int mi = 0; mi < 2; mi++)
                mma_f16(acc[mi][ni], a[mi], b[ni]);
    }
}

// ===========================================================================
// Prep kernels
// ===========================================================================
__global__ void pack_x_kernel(const float* __restrict__ x) {
    size_t e = ((size_t)blockIdx.x * 256 + threadIdx.x) * 4;
    float4 v = *(const float4*)(x + e);
    uint2 p;
    p.x = h2u(v.x, v.y);
    p.y = h2u(v.z, v.w);
    *(uint2*)&g_xf[e] = p;
}

__global__ void pack_w_kernel(const float* __restrict__ Wq, const float* __restrict__ Wkv,
                              const float* __restrict__ Wo) {
    size_t e0 = ((size_t)blockIdx.x * 256 + threadIdx.x) * 4;
    #pragma unroll
    for (int cc = 0; cc < 4; cc++) {
        size_t e = e0 + cc;
        if (e < 262144) {
            int k = (int)(e & 511), n = (int)(e >> 9);
            g_wqf[e] = __float2half(Wq[(size_t)k * 512 + n]);
        } else if (e < 786432) {
            size_t m = e - 262144;
            int k = (int)(m & 511), n = (int)(m >> 9);
            g_wkvf[m] = __float2half(Wkv[(size_t)k * 1024 + n]);
        } else {
            size_t m = e - 786432;
            int k = (int)(m & 511), n = (int)(m >> 9);
            g_wof[m] = __float2half(Wo[(size_t)k * 512 + n]);
        }
    }
}

__global__ void pack_t_kernel(const float* __restrict__ T) {
    size_t e0 = ((size_t)blockIdx.x * 256 + threadIdx.x) * 4;
    #pragma unroll
    for (int cc = 0; cc < 4; cc++) {
        size_t e = e0 + cc;
        int p = (int)(e >> 6), d = (int)(e & 63);
        g_tf[e] = __float2half((p < NPp) ? T[(size_t)p * 64 + d] : 0.f);
    }
}

// ===========================================================================
// GEMM 1: QKV.  q scaled by 0.125*log2(e) (exp2 softmax domain).
// ===========================================================================
__global__ __launch_bounds__(256) void mm_qkv() {
    extern __shared__ uint8_t smem[];
    const uint32_t sb = smem_u32(smem);
    const int t = threadIdx.x, lane = t & 31, wid = t >> 5;
    const int wy = wid >> 1, nx = wid & 1;
    const int n0 = blockIdx.x * 64, m0 = blockIdx.y * 128;

    const h16* A = g_xf + (size_t)m0 * 512;
    const h16* B = (n0 < 512) ? (g_wqf + (size_t)n0 * 512) : (g_wkvf + (size_t)(n0 - 512) * 512);

    float acc[2][4][4] = {};
    stage_cp<128, 256>(sb, A, 512, t);
    stage_cp<64, 256>(sb + B_OFF, B, 512, t);
    CP_COMMIT();
    for (int s = 0; s < 8; s++) {
        if (s + 1 < 8) {
            uint32_t nb = sb + ((s + 1) & 1) * BUFB;
            stage_cp<128, 256>(nb, A + (s + 1) * 64, 512, t);
            stage_cp<64, 256>(nb + B_OFF, B + (s + 1) * 64, 512, t);
            CP_COMMIT();
            CP_WAIT(1);
        } else {
            CP_WAIT(0);
        }
        __syncthreads();
        uint32_t buf = sb + (s & 1) * BUFB;
        compute_stage(buf + (uint32_t)(wy * 32) * STRB + lda_off(lane),
                      buf + B_OFF + (uint32_t)(nx * 32) * STRB + ldb_off(lane), acc);
        __syncthreads();
    }

    const int b = m0 >> 10, i0 = m0 & 1023;
    const int region = n0 >> 9;
    const int h = (n0 >> 6) & 7;
    const int bh_idx = b * 8 + h;
    const int r = lane >> 2, cc = lane & 3;
    const float sc = (region == 0) ? 0.125f * 1.44269504f : 1.0f;

    if (region == 2) {
        #pragma unroll
        for (int mi = 0; mi < 2; mi++)
        #pragma unroll
        for (int ni = 0; ni < 4; ni++)
        #pragma unroll
        for (int g = 0; g < 2; g++) {
            int i = i0 + wy * 32 + mi * 16 + r + g * 8;
            int d = nx * 32 + ni * 8 + cc * 2;
            g_vtf[((size_t)bh_idx * 64 + d)     * 1024 + i] = __float2half(acc[mi][ni][2 * g]);
            g_vtf[((size_t)bh_idx * 64 + d + 1) * 1024 + i] = __float2half(acc[mi][ni][2 * g + 1]);
        }
    } else {
        h16* dst = (region == 0 ? g_qf : g_kf) + ((size_t)bh_idx * 1024 + i0) * 64;
        #pragma unroll
        for (int mi = 0; mi < 2; mi++)
        #pragma unroll
        for (int ni = 0; ni < 4; ni++)
        #pragma unroll
        for (int g = 0; g < 2; g++) {
            int il = wy * 32 + mi * 16 + r + g * 8;
            int d  = nx * 32 + ni * 8 + cc * 2;
            *(uint32_t*)&dst[(size_t)il * 64 + d] =
                h2u(sc * acc[mi][ni][2 * g], sc * acc[mi][ni][2 * g + 1]);
        }
    }
}

// ===========================================================================
// GEMM 2: pos dots, scattered into GATHERED layout Pg[m][j], j = i-(p-512).
// grid(512), 256 thr, persistent A, 17 double-buffered T-tiles.
// ===========================================================================
__global__ __launch_bounds__(256) void mm_pos() {
    extern __shared__ uint8_t smem[];
    const uint32_t sb = smem_u32(smem);
    const int t = threadIdx.x, lane = t & 31, wid = t >> 5;
    const int wy = wid >> 1, nx = wid & 1;
    const int m0 = blockIdx.x * 128;
    const int r = lane >> 2, cc = lane & 3;

    stage_cp<128, 256>(sb, g_qf + (size_t)m0 * 64, 64, t);
    stage_cp<64, 256>(sb + PB0, g_tf, 64, t);
    CP_COMMIT();

    const uint32_t a_base = sb + (uint32_t)(wy * 32) * STRB + lda_off(lane);

    for (int pt = 0; pt < 17; pt++) {
        if (pt + 1 < 17) {
            stage_cp<64, 256>(sb + PB0 + ((pt + 1) & 1) * 9216u,
                              g_tf + (size_t)(pt + 1) * 64 * 64, 64, t);
            CP_COMMIT();
            CP_WAIT(1);
        } else {
            CP_WAIT(0);
        }
        __syncthreads();

        float acc[2][4][4] = {};
        uint32_t b_base = sb + PB0 + (uint32_t)(pt & 1) * 9216u
                        + (uint32_t)(nx * 32) * STRB + ldb_off(lane);
        compute_stage(a_base, b_base, acc);

        const int p0 = pt * 64;
        #pragma unroll
        for (int mi = 0; mi < 2; mi++)
        #pragma unroll
        for (int ni = 0; ni < 4; ni++)
        #pragma unroll
        for (int g = 0; g < 2; g++) {
            int m = m0 + wy * 32 + mi * 16 + r + g * 8;
            int i = m & 1023;
            int pp = p0 + nx * 32 + ni * 8 + cc * 2;
            #pragma unroll
            for (int e2 = 0; e2 < 2; e2++) {
                int p = pp + e2;
                int j = i - p + 512;
                if (p <= 1024 && j >= 0 && j < 1024)
                    g_Pg[(size_t)m * 1024 + j] = __float2half(acc[mi][ni][2 * g + e2]);
            }
        }
        __syncthreads();
    }
}

// ===========================================================================
// Edge fill: Pg[m][j] = Pg[m][clamp(j, i-512, i+512)]
// ===========================================================================
__global__ void pos_fill_kernel() {
    const int m = blockIdx.x;              // 0..65535
    const int i = m & 1023;
    const int t = threadIdx.x;
    h16* row = g_Pg + (size_t)m * 1024;
    if (i > 512) {
        h16 val = row[i - 512];
        for (int j = t; j < i - 512; j += 128) row[j] = val;
    }
    if (i < 511) {
        h16 val = row[i + 512];
        for (int j = i + 513 + t; j < 1024; j += 128) row[j] = val;
    }
}

// ===========================================================================
// Fused attention: grid(8, 64), 256 thr.  Warp owns 16 rows x all 64 j.
// P tile streamed via cp.async; exp2 softmax domain.
// ===========================================================================
static __device__ __forceinline__ void fa_stage_kvp(uint32_t kvb,
                                                    const h16* k, const h16* v,
                                                    const h16* pg, int j0, int t) {
    stage_cp<64, 256>(kvb + FK, k + (size_t)j0 * 64, 64, t);
    stage_cp<64, 256>(kvb + FV, v + j0, 1024, t);
    stage_cp<128, 256>(kvb + FP, pg + j0, 1024, t);
    CP_COMMIT();
}

__global__ __launch_bounds__(256) void fa_kernel() {
    extern __shared__ uint8_t smem[];
    const uint32_t sb = smem_u32(smem);
    const int t = threadIdx.x, lane = t & 31, wid = t >> 5;
    const int r = lane >> 2, cc = lane & 3;
    const int i0 = blockIdx.x * 128, bh = blockIdx.y;

    const h16* q = g_qf + ((size_t)bh * 1024 + i0) * 64;
    const h16* k = g_kf + (size_t)bh * 1024 * 64;
    const h16* v = g_vtf + (size_t)bh * 64 * 1024;
    const h16* pg = g_Pg + ((size_t)bh * 1024 + i0) * 1024;

    stage_cp<128, 256>(sb + FQ, q, 64, t);
    fa_stage_kvp(sb + FKV0, k, v, pg, 0, t);

    const uint32_t q_base = sb + FQ + (uint32_t)(wid * 16) * STRB + lda_off(lane);
    const uint32_t k_rel  = FK + ldb_off(lane);
    const uint32_t v_rel  = FV + ldb_off(lane);
    const uint32_t p_rel  = FP + (uint32_t)(wid * 16 + r) * STRB + (uint32_t)(cc * 4);

    float m_run[2] = {-1e30f, -1e30f};
    float l_run[2] = {0.f, 0.f};
    float oacc[8][4] = {};

    for (int jt = 0; jt < 16; jt++) {
        const uint32_t kvb = sb + FKV0 + (uint32_t)(jt & 1) * FKVSTR;
        if (jt + 1 < 16) {
            fa_stage_kvp(sb + FKV0 + (uint32_t)((jt + 1) & 1) * FKVSTR, k, v, pg, (jt + 1) * 64, t);
            CP_WAIT(1);
        } else {
            CP_WAIT(0);
        }
        __syncthreads();

        // ---- QK^T: this warp's 16 rows x all 64 cols ----
        float sacc[8][4] = {};
        #pragma unroll
        for (int ks = 0; ks < 4; ks++) {
            uint32_t qa[4], kb[8][2];
            LDMX4(qa[0], qa[1], qa[2], qa[3], q_base + (uint32_t)(ks * 32));
            #pragma unroll
            for (int p3 = 0; p3 < 4; p3++) {
                uint32_t bd = kvb + k_rel + (uint32_t)(p3 * 16) * STRB + (uint32_t)(ks * 32);
                LDMX4(kb[2 * p3][0], kb[2 * p3][1], kb[2 * p3 + 1][0], kb[2 * p3 + 1][1], bd);
            }
            #pragma unroll
            for (int ni = 0; ni < 8; ni++)
                mma_f16(sacc[ni], qa, kb[ni]);
        }

        // ---- positional term from smem (conflict-free LDS.32) ----
        #pragma unroll
        for (int ni = 0; ni < 8; ni++)
            #pragma unroll
            for (int g = 0; g < 2; g++) {
                uint32_t pv;
                LDS32(pv, kvb + p_rel + (uint32_t)(g * 8) * STRB + (uint32_t)(ni * 16));
                __half2 ph = *(__half2*)&pv;
                float2 pf = __half22float2(ph);
                sacc[ni][2 * g]     += pf.x;
                sacc[ni][2 * g + 1] += pf.y;
            }

        // ---- warp-local online softmax (exp2 domain) ----
        float mnew[2], f[2];
        #pragma unroll
        for (int g = 0; g < 2; g++) {
            float m = fmaxf(sacc[0][2 * g], sacc[0][2 * g + 1]);
            #pragma unroll
            for (int ni = 1; ni < 8; ni++)
                m = fmaxf(m, fmaxf(sacc[ni][2 * g], sacc[ni][2 * g + 1]));
            m = fmaxf(m, __shfl_xor_sync(0xffffffffu, m, 1));
            m = fmaxf(m, __shfl_xor_sync(0xffffffffu, m, 2));
            float mn = fmaxf(m_run[g], m);
            f[g] = ex2(m_run[g] - mn);
            m_run[g] = mn;
            mnew[g] = mn;
        }
        #pragma unroll
        for (int ni = 0; ni < 8; ni++)
            #pragma unroll
            for (int e = 0; e < 4; e++)
                sacc[ni][e] = ex2(sacc[ni][e] - mnew[e >> 1]);
        #pragma unroll
        for (int g = 0; g < 2; g++) {
            float s = 0.f;
            #pragma unroll
            for (int ni = 0; ni < 8; ni++)
                s += sacc[ni][2 * g] + sacc[ni][2 * g + 1];
            s += __shfl_xor_sync(0xffffffffu, s, 1);
            s += __shfl_xor_sync(0xffffffffu, s, 2);
            l_run[g] = l_run[g] * f[g] + s;
        }
        #pragma unroll
        for (int dn = 0; dn < 8; dn++)
            #pragma unroll
            for (int e = 0; e < 4; e++)
                oacc[dn][e] *= f[e >> 1];

        // ---- SV: p fragments via C->A identity; B = V^T ----
        #pragma unroll
        for (int c = 0; c < 4; c++) {
            uint32_t vb[8][2];
            #pragma unroll
            for (int p3 = 0; p3 < 4; p3++) {
                uint32_t vd = kvb + v_rel + (uint32_t)(p3 * 16) * STRB + (uint32_t)(c * 32);
                LDMX4(vb[2 * p3][0], vb[2 * p3][1], vb[2 * p3 + 1][0], vb[2 * p3 + 1][1], vd);
            }
            uint32_t pa[4];
            pa[0] = h2u(sacc[2 * c][0],     sacc[2 * c][1]);
            pa[1] = h2u(sacc[2 * c][2],     sacc[2 * c][3]);
            pa[2] = h2u(sacc[2 * c + 1][0], sacc[2 * c + 1][1]);
            pa[3] = h2u(sacc[2 * c + 1][2], sacc[2 * c + 1][3]);
            #pragma unroll
            for (int dn = 0; dn < 8; dn++)
                mma_f16(oacc[dn], pa, vb[dn]);
        }
        __syncthreads();
    }

    // ---- epilogue: O /= l, write ctx fp16 ----
    const int b = bh >> 3, hh = bh & 7;
    float inv[2] = {1.0f / l_run[0], 1.0f / l_run[1]};
    #pragma unroll
    for (int dn = 0; dn < 8; dn++)
    #pragma unroll
    for (int g = 0; g < 2; g++) {
        int gi = i0 + wid * 16 + g * 8 + r;
        int d  = dn * 8 + cc * 2;
        size_t off = ((size_t)(b * 1024 + gi)) * 512 + hh * 64 + d;
        *(uint32_t*)&g_cf[off] = h2u(oacc[dn][2 * g] * inv[g], oacc[dn][2 * g + 1] * inv[g]);
    }
}

// ===========================================================================
// GEMM 5: out = ctx @ Wo + bo.  grid(8, 64), 256 thr.
// ===========================================================================
__global__ __launch_bounds__(256) void mm_out(const float* __restrict__ bo,
                                              float* __restrict__ out) {
    extern __shared__ uint8_t smem[];
    const uint32_t sb = smem_u32(smem);
    const int t = threadIdx.x, lane = t & 31, wid = t >> 5;
    const int wy = wid >> 1, nx = wid & 1;
    const int n0 = blockIdx.x * 64, m0 = blockIdx.y * 128;

    const h16* A = g_cf + (size_t)m0 * 512;
    const h16* B = g_wof + (size_t)n0 * 512;

    float acc[2][4][4] = {};
    stage_cp<128, 256>(sb, A, 512, t);
    stage_cp<64, 256>(sb + B_OFF, B, 512, t);
    CP_COMMIT();
    for (int s = 0; s < 8; s++) {
        if (s + 1 < 8) {
            uint32_t nb = sb + ((s + 1) & 1) * BUFB;
            stage_cp<128, 256>(nb, A + (s + 1) * 64, 512, t);
            stage_cp<64, 256>(nb + B_OFF, B + (s + 1) * 64, 512, t);
            CP_COMMIT();
            CP_WAIT(1);
        } else {
            CP_WAIT(0);
        }
        __syncthreads();
        uint32_t buf = sb + (s & 1) * BUFB;
        compute_stage(buf + (uint32_t)(wy * 32) * STRB + lda_off(lane),
                      buf + B_OFF + (uint32_t)(nx * 32) * STRB + ldb_off(lane), acc);
        __syncthreads();
    }

    const int r = lane >> 2, cc = lane & 3;
    #pragma unroll
    for (int mi = 0; mi < 2; mi++)
    #pragma unroll
    for (int ni = 0; ni < 4; ni++)
    #pragma unroll
    for (int g = 0; g < 2; g++) {
        int m = m0 + wy * 32 + mi * 16 + r + g * 8;
        int n = n0 + nx * 32 + ni * 8 + cc * 2;
        float2 o;
        o.x = acc[mi][ni][2 * g]     + bo[n];
        o.y = acc[mi][ni][2 * g + 1] + bo[n + 1];
        *(float2*)&out[(size_t)m * 512 + n] = o;
    }
}

// ===========================================================================
extern "C" void kernel_launch(void* const* d_in, const int* in_sizes, int n_in,
                              void* d_out, int out_size) {
    const float* x   = (const float*)d_in[0];
    const float* Wq  = (const float*)d_in[1];
    const float* Wkv = (const float*)d_in[2];
    const float* Wo  = (const float*)d_in[3];
    const float* bo  = (const float*)d_in[4];
    const float* pos = (const float*)d_in[5];
    float* out = (float*)d_out;

    cudaFuncSetAttribute(mm_qkv,    cudaFuncAttributeMaxDynamicSharedMemorySize, SMEM_G);
    cudaFuncSetAttribute(mm_pos,    cudaFuncAttributeMaxDynamicSharedMemorySize, SMEM_POS);
    cudaFuncSetAttribute(fa_kernel, cudaFuncAttributeMaxDynamicSharedMemorySize, SMEM_FA);
    cudaFuncSetAttribute(mm_out,    cudaFuncAttributeMaxDynamicSharedMemorySize, SMEM_G);

    pack_x_kernel<<<4096, 256>>>(x);
    pack_w_kernel<<<1024, 256>>>(Wq, Wkv, Wo);
    pack_t_kernel<<<68, 256>>>(pos);

    mm_qkv   <<<dim3(24, 64), 256, SMEM_G>>>();
    mm_pos   <<<512,          256, SMEM_POS>>>();
    pos_fill_kernel<<<65536, 128>>>();
    fa_kernel<<<dim3(8, 64),  256, SMEM_FA>>>();
    mm_out   <<<dim3(8, 64),  256, SMEM_G>>>(bo, out);
}

// round 15
// speedup vs baseline: 1.1789x; 1.1789x over previous
#include <cuda_runtime.h>
#include <cuda_fp16.h>
#include <cstdint>

#define Nn    1024
#define NPp   1025
#define NPS   1028
#define BHb   64
#define MXm   8192

typedef __half h16;

// ---------------- device scratch (all fp16) ----------------
__device__ h16 g_xf [(size_t)MXm * 512];
__device__ h16 g_wqf[(size_t)512 * 512];        // [n][k]
__device__ h16 g_wkvf[(size_t)1024 * 512];      // [n][k]
__device__ h16 g_wof[(size_t)512 * 512];        // [n][k]
__device__ h16 g_tf [(size_t)1088 * 64];        // pos table (padded)
__device__ h16 g_qf [(size_t)BHb * Nn * 64];    // scaled by 0.125*log2e
__device__ h16 g_kf [(size_t)BHb * Nn * 64];
__device__ h16 g_vtf[(size_t)BHb * 64 * Nn];    // v^T [bh][d][j]
__device__ h16 g_cf [(size_t)MXm * 512];        // ctx [b,n][h*d]
__device__ h16 g_Ph [(size_t)BHb * Nn * NPS];   // pos dots (scaled, exp2 domain)

// ---------------- smem geometry ----------------
#define STRB  144
// GEMM kernels (qkv/out): A 128 rows + B 64 rows, 2 stages
#define B_OFF  18432u
#define BUFB   27648u
#define SMEM_G 55296
// pos: A 128 rows persistent + 2x B 64 rows
#define PB0      18432u
#define SMEM_POS 36864
// fused attention: Q 128 rows + 2x (K 64 + V 64)
#define FQ      0u
#define FKV0    18432u
#define FKVSTR  18432u
#define FK      0u
#define FV      9216u
#define SMEM_FA 55296

#define CP16(d, s)  asm volatile("cp.async.ca.shared.global [%0], [%1], 16;" :: "r"(d), "l"(s))
#define CP_COMMIT() asm volatile("cp.async.commit_group;" ::: "memory")
#define CP_WAIT(n)  asm volatile("cp.async.wait_group %0;" :: "n"(n) : "memory")

#define LDMX4(r0, r1, r2, r3, a) \
    asm volatile("ldmatrix.sync.aligned.m8n8.x4.shared.b16 {%0,%1,%2,%3}, [%4];" \
                 : "=r"(r0), "=r"(r1), "=r"(r2), "=r"(r3) : "r"(a))

static __device__ __forceinline__ uint32_t smem_u32(const void* p) {
    uint32_t a;
    asm("{ .reg .u64 t; cvta.to.shared.u64 t, %1; cvt.u32.u64 %0, t; }" : "=r"(a) : "l"(p));
    return a;
}
static __device__ __forceinline__ float ex2(float x) {
    float y;
    asm("ex2.approx.f32 %0, %1;" : "=f"(y) : "f"(x));
    return y;
}
static __device__ __forceinline__ void mma_f16(float* d, const uint32_t* a, const uint32_t* b) {
    asm volatile("mma.sync.aligned.m16n8k16.row.col.f32.f16.f16.f32 "
                 "{%0,%1,%2,%3}, {%4,%5,%6,%7}, {%8,%9}, {%0,%1,%2,%3};"
                 : "+f"(d[0]), "+f"(d[1]), "+f"(d[2]), "+f"(d[3])
                 : "r"(a[0]), "r"(a[1]), "r"(a[2]), "r"(a[3]), "r"(b[0]), "r"(b[1]));
}
static __device__ __forceinline__ uint32_t h2u(float a, float b) {
    __half2 h = __floats2half2_rn(a, b);
    return *(uint32_t*)&h;
}

template <int R, int T>
static __device__ __forceinline__ void stage_cp(uint32_t sdst, const h16* src, int lds, int t) {
    #pragma unroll
    for (int i = 0; i < R * 8 / T; i++) {
        int idx = t + i * T;
        int row = idx >> 3, ch = idx & 7;
        CP16(sdst + (uint32_t)row * STRB + (uint32_t)ch * 16,
             src + (size_t)row * lds + ch * 8);
    }
}

static __device__ __forceinline__ uint32_t lda_off(int lane) {
    return (uint32_t)(lane & 15) * STRB + (uint32_t)(lane & 16);
}
static __device__ __forceinline__ uint32_t ldb_off(int lane) {
    return (uint32_t)((lane & 7) + ((lane & 16) >> 1)) * STRB + (uint32_t)((lane & 8) << 1);
}

// single-term K=64 stage; warp tile 32x32
static __device__ __forceinline__ void compute_stage(uint32_t a_base, uint32_t b_base,
                                                     float acc[2][4][4]) {
    #pragma unroll
    for (int ks = 0; ks < 4; ks++) {
        uint32_t a[2][4], b[4][2];
        #pragma unroll
        for (int mi = 0; mi < 2; mi++) {
            uint32_t ad = a_base + (uint32_t)(mi * 16) * STRB + (uint32_t)(ks * 32);
            LDMX4(a[mi][0], a[mi][1], a[mi][2], a[mi][3], ad);
        }
        #pragma unroll
        for (int p = 0; p < 2; p++) {
            uint32_t bd = b_base + (uint32_t)(p * 16) * STRB + (uint32_t)(ks * 32);
            LDMX4(b[2 * p][0], b[2 * p][1], b[2 * p + 1][0], b[2 * p + 1][1], bd);
        }
        #pragma unroll
        for (int ni = 0; ni < 4; ni++)
            #pragma unroll
            for (int mi = 0; mi < 2; mi++)
                mma_f16(acc[mi][ni], a[mi], b[ni]);
    }
}

// ===========================================================================
// Prep kernels
// ===========================================================================
__global__ void pack_x_kernel(const float* __restrict__ x) {
    size_t e = ((size_t)blockIdx.x * 256 + threadIdx.x) * 4;
    float4 v = *(const float4*)(x + e);
    uint2 p;
    p.x = h2u(v.x, v.y);
    p.y = h2u(v.z, v.w);
    *(uint2*)&g_xf[e] = p;
}

__global__ void pack_w_kernel(const float* __restrict__ Wq, const float* __restrict__ Wkv,
                              const float* __restrict__ Wo) {
    size_t e0 = ((size_t)blockIdx.x * 256 + threadIdx.x) * 4;
    #pragma unroll
    for (int cc = 0; cc < 4; cc++) {
        size_t e = e0 + cc;
        if (e < 262144) {
            int k = (int)(e & 511), n = (int)(e >> 9);
            g_wqf[e] = __float2half(Wq[(size_t)k * 512 + n]);
        } else if (e < 786432) {
            size_t m = e - 262144;
            int k = (int)(m & 511), n = (int)(m >> 9);
            g_wkvf[m] = __float2half(Wkv[(size_t)k * 1024 + n]);
        } else {
            size_t m = e - 786432;
            int k = (int)(m & 511), n = (int)(m >> 9);
            g_wof[m] = __float2half(Wo[(size_t)k * 512 + n]);
        }
    }
}

__global__ void pack_t_kernel(const float* __restrict__ T) {
    size_t e0 = ((size_t)blockIdx.x * 256 + threadIdx.x) * 4;
    #pragma unroll
    for (int cc = 0; cc < 4; cc++) {
        size_t e = e0 + cc;
        int p = (int)(e >> 6), d = (int)(e & 63);
        g_tf[e] = __float2half((p < NPp) ? T[(size_t)p * 64 + d] : 0.f);
    }
}

// ===========================================================================
// GEMM 1: QKV.  q scaled by 0.125*log2(e) (exp2 softmax domain).
// ===========================================================================
__global__ __launch_bounds__(256) void mm_qkv() {
    extern __shared__ uint8_t smem[];
    const uint32_t sb = smem_u32(smem);
    const int t = threadIdx.x, lane = t & 31, wid = t >> 5;
    const int wy = wid >> 1, nx = wid & 1;
    const int n0 = blockIdx.x * 64, m0 = blockIdx.y * 128;

    const h16* A = g_xf + (size_t)m0 * 512;
    const h16* B = (n0 < 512) ? (g_wqf + (size_t)n0 * 512) : (g_wkvf + (size_t)(n0 - 512) * 512);

    float acc[2][4][4] = {};
    stage_cp<128, 256>(sb, A, 512, t);
    stage_cp<64, 256>(sb + B_OFF, B, 512, t);
    CP_COMMIT();
    for (int s = 0; s < 8; s++) {
        if (s + 1 < 8) {
            uint32_t nb = sb + ((s + 1) & 1) * BUFB;
            stage_cp<128, 256>(nb, A + (s + 1) * 64, 512, t);
            stage_cp<64, 256>(nb + B_OFF, B + (s + 1) * 64, 512, t);
            CP_COMMIT();
            CP_WAIT(1);
        } else {
            CP_WAIT(0);
        }
        __syncthreads();
        uint32_t buf = sb + (s & 1) * BUFB;
        compute_stage(buf + (uint32_t)(wy * 32) * STRB + lda_off(lane),
                      buf + B_OFF + (uint32_t)(nx * 32) * STRB + ldb_off(lane), acc);
        __syncthreads();
    }

    const int b = m0 >> 10, i0 = m0 & 1023;
    const int region = n0 >> 9;
    const int h = (n0 >> 6) & 7;
    const int bh_idx = b * 8 + h;
    const int r = lane >> 2, cc = lane & 3;
    const float sc = (region == 0) ? 0.125f * 1.44269504f : 1.0f;

    if (region == 2) {
        #pragma unroll
        for (int mi = 0; mi < 2; mi++)
        #pragma unroll
        for (int ni = 0; ni < 4; ni++)
        #pragma unroll
        for (int g = 0; g < 2; g++) {
            int i = i0 + wy * 32 + mi * 16 + r + g * 8;
            int d = nx * 32 + ni * 8 + cc * 2;
            g_vtf[((size_t)bh_idx * 64 + d)     * 1024 + i] = __float2half(acc[mi][ni][2 * g]);
            g_vtf[((size_t)bh_idx * 64 + d + 1) * 1024 + i] = __float2half(acc[mi][ni][2 * g + 1]);
        }
    } else {
        h16* dst = (region == 0 ? g_qf : g_kf) + ((size_t)bh_idx * 1024 + i0) * 64;
        #pragma unroll
        for (int mi = 0; mi < 2; mi++)
        #pragma unroll
        for (int ni = 0; ni < 4; ni++)
        #pragma unroll
        for (int g = 0; g < 2; g++) {
            int il = wy * 32 + mi * 16 + r + g * 8;
            int d  = nx * 32 + ni * 8 + cc * 2;
            *(uint32_t*)&dst[(size_t)il * 64 + d] =
                h2u(sc * acc[mi][ni][2 * g], sc * acc[mi][ni][2 * g + 1]);
        }
    }
}

// ===========================================================================
// GEMM 2: P = q_scaled . T^T -> fp16 (exp2 domain inherited from q).
// grid(512), 256 thr, persistent A, 17 double-buffered T-tiles.
// ===========================================================================
__global__ __launch_bounds__(256) void mm_pos() {
    extern __shared__ uint8_t smem[];
    const uint32_t sb = smem_u32(smem);
    const int t = threadIdx.x, lane = t & 31, wid = t >> 5;
    const int wy = wid >> 1, nx = wid & 1;
    const int m0 = blockIdx.x * 128;
    const int r = lane >> 2, cc = lane & 3;

    stage_cp<128, 256>(sb, g_qf + (size_t)m0 * 64, 64, t);
    stage_cp<64, 256>(sb + PB0, g_tf, 64, t);
    CP_COMMIT();

    const uint32_t a_base = sb + (uint32_t)(wy * 32) * STRB + lda_off(lane);

    for (int pt = 0; pt < 17; pt++) {
        if (pt + 1 < 17) {
            stage_cp<64, 256>(sb + PB0 + ((pt + 1) & 1) * 9216u,
                              g_tf + (size_t)(pt + 1) * 64 * 64, 64, t);
            CP_COMMIT();
            CP_WAIT(1);
        } else {
            CP_WAIT(0);
        }
        __syncthreads();

        float acc[2][4][4] = {};
        uint32_t b_base = sb + PB0 + (uint32_t)(pt & 1) * 9216u
                        + (uint32_t)(nx * 32) * STRB + ldb_off(lane);
        compute_stage(a_base, b_base, acc);

        const int p0 = pt * 64;
        #pragma unroll
        for (int mi = 0; mi < 2; mi++)
        #pragma unroll
        for (int ni = 0; ni < 4; ni++)
        #pragma unroll
        for (int g = 0; g < 2; g++) {
            int m = m0 + wy * 32 + mi * 16 + r + g * 8;
            int p = p0 + nx * 32 + ni * 8 + cc * 2;
            if (p + 1 < NPp) {
                *(uint32_t*)&g_Ph[(size_t)m * NPS + p] =
                    h2u(acc[mi][ni][2 * g], acc[mi][ni][2 * g + 1]);
            } else if (p < NPp) {
                g_Ph[(size_t)m * NPS + p] = __float2half(acc[mi][ni][2 * g]);
            }
        }
        __syncthreads();
    }
}

// ===========================================================================
// Fused attention: grid(8, 64), 256 thr.  Warp owns 16 rows x all 64 j;
// warp-local online softmax in exp2 domain; scattered fp16 P gather (__ldg).
// ===========================================================================
static __device__ __forceinline__ void fa_stage_kv(uint32_t kvb,
                                                   const h16* k, const h16* v, int j0, int t) {
    stage_cp<64, 256>(kvb + FK, k + (size_t)j0 * 64, 64, t);
    stage_cp<64, 256>(kvb + FV, v + j0, 1024, t);
    CP_COMMIT();
}

__global__ __launch_bounds__(256) void fa_kernel() {
    extern __shared__ uint8_t smem[];
    const uint32_t sb = smem_u32(smem);
    const int t = threadIdx.x, lane = t & 31, wid = t >> 5;
    const int r = lane >> 2, cc = lane & 3;
    const int i0 = blockIdx.x * 128, bh = blockIdx.y;

    const h16* q = g_qf + ((size_t)bh * 1024 + i0) * 64;
    const h16* k = g_kf + (size_t)bh * 1024 * 64;
    const h16* v = g_vtf + (size_t)bh * 64 * 1024;
    const h16* Pb = g_Ph + (size_t)bh * 1024 * NPS;

    stage_cp<128, 256>(sb + FQ, q, 64, t);
    fa_stage_kv(sb + FKV0, k, v, 0, t);

    const uint32_t q_base = sb + FQ + (uint32_t)(wid * 16) * STRB + lda_off(lane);
    const uint32_t k_rel  = FK + ldb_off(lane);
    const uint32_t v_rel  = FV + ldb_off(lane);

    float m_run[2] = {-1e30f, -1e30f};
    float l_run[2] = {0.f, 0.f};
    float oacc[8][4] = {};

    for (int jt = 0; jt < 16; jt++) {
        const uint32_t kvb = sb + FKV0 + (uint32_t)(jt & 1) * FKVSTR;
        if (jt + 1 < 16) {
            fa_stage_kv(sb + FKV0 + (uint32_t)((jt + 1) & 1) * FKVSTR, k, v, (jt + 1) * 64, t);
            CP_WAIT(1);
        } else {
            CP_WAIT(0);
        }
        __syncthreads();

        // ---- QK^T: this warp's 16 rows x all 64 cols ----
        float sacc[8][4] = {};
        #pragma unroll
        for (int ks = 0; ks < 4; ks++) {
            uint32_t qa[4], kb[8][2];
            LDMX4(qa[0], qa[1], qa[2], qa[3], q_base + (uint32_t)(ks * 32));
            #pragma unroll
            for (int p3 = 0; p3 < 4; p3++) {
                uint32_t bd = kvb + k_rel + (uint32_t)(p3 * 16) * STRB + (uint32_t)(ks * 32);
                LDMX4(kb[2 * p3][0], kb[2 * p3][1], kb[2 * p3 + 1][0], kb[2 * p3 + 1][1], bd);
            }
            #pragma unroll
            for (int ni = 0; ni < 8; ni++)
                mma_f16(sacc[ni], qa, kb[ni]);
        }

        // ---- positional term (scattered fp16 gather, __ldg) ----
        const int j0 = jt * 64;
        #pragma unroll
        for (int ni = 0; ni < 8; ni++)
            #pragma unroll
            for (int e = 0; e < 4; e++) {
                int i = i0 + wid * 16 + (e >> 1) * 8 + r;
                int j = j0 + ni * 8 + cc * 2 + (e & 1);
                int dd = i - j;
                dd = max(-512, min(512, dd));
                sacc[ni][e] += __half2float(__ldg(&Pb[(size_t)i * NPS + dd + 512]));
            }

        // ---- warp-local online softmax (exp2 domain) ----
        float mnew[2], f[2];
        #pragma unroll
        for (int g = 0; g < 2; g++) {
            float m = fmaxf(sacc[0][2 * g], sacc[0][2 * g + 1]);
            #pragma unroll
            for (int ni = 1; ni < 8; ni++)
                m = fmaxf(m, fmaxf(sacc[ni][2 * g], sacc[ni][2 * g + 1]));
            m = fmaxf(m, __shfl_xor_sync(0xffffffffu, m, 1));
            m = fmaxf(m, __shfl_xor_sync(0xffffffffu, m, 2));
            float mn = fmaxf(m_run[g], m);
            f[g] = ex2(m_run[g] - mn);
            m_run[g] = mn;
            mnew[g] = mn;
        }
        #pragma unroll
        for (int ni = 0; ni < 8; ni++)
            #pragma unroll
            for (int e = 0; e < 4; e++)
                sacc[ni][e] = ex2(sacc[ni][e] - mnew[e >> 1]);
        #pragma unroll
        for (int g = 0; g < 2; g++) {
            float s = 0.f;
            #pragma unroll
            for (int ni = 0; ni < 8; ni++)
                s += sacc[ni][2 * g] + sacc[ni][2 * g + 1];
            s += __shfl_xor_sync(0xffffffffu, s, 1);
            s += __shfl_xor_sync(0xffffffffu, s, 2);
            l_run[g] = l_run[g] * f[g] + s;
        }
        #pragma unroll
        for (int dn = 0; dn < 8; dn++)
            #pragma unroll
            for (int e = 0; e < 4; e++)
                oacc[dn][e] *= f[e >> 1];

        // ---- SV: p fragments via C->A identity; B = V^T ----
        #pragma unroll
        for (int c = 0; c < 4; c++) {
            uint32_t vb[8][2];
            #pragma unroll
            for (int p3 = 0; p3 < 4; p3++) {
                uint32_t vd = kvb + v_rel + (uint32_t)(p3 * 16) * STRB + (uint32_t)(c * 32);
                LDMX4(vb[2 * p3][0], vb[2 * p3][1], vb[2 * p3 + 1][0], vb[2 * p3 + 1][1], vd);
            }
            uint32_t pa[4];
            pa[0] = h2u(sacc[2 * c][0],     sacc[2 * c][1]);
            pa[1] = h2u(sacc[2 * c][2],     sacc[2 * c][3]);
            pa[2] = h2u(sacc[2 * c + 1][0], sacc[2 * c + 1][1]);
            pa[3] = h2u(sacc[2 * c + 1][2], sacc[2 * c + 1][3]);
            #pragma unroll
            for (int dn = 0; dn < 8; dn++)
                mma_f16(oacc[dn], pa, vb[dn]);
        }
        __syncthreads();
    }

    // ---- epilogue: O /= l, write ctx fp16 ----
    const int b = bh >> 3, hh = bh & 7;
    float inv[2] = {1.0f / l_run[0], 1.0f / l_run[1]};
    #pragma unroll
    for (int dn = 0; dn < 8; dn++)
    #pragma unroll
    for (int g = 0; g < 2; g++) {
        int gi = i0 + wid * 16 + g * 8 + r;
        int d  = dn * 8 + cc * 2;
        size_t off = ((size_t)(b * 1024 + gi)) * 512 + hh * 64 + d;
        *(uint32_t*)&g_cf[off] = h2u(oacc[dn][2 * g] * inv[g], oacc[dn][2 * g + 1] * inv[g]);
    }
}

// ===========================================================================
// GEMM 5: out = ctx @ Wo + bo.  grid(8, 64), 256 thr.
// ===========================================================================
__global__ __launch_bounds__(256) void mm_out(const float* __restrict__ bo,
                                              float* __restrict__ out) {
    extern __shared__ uint8_t smem[];
    const uint32_t sb = smem_u32(smem);
    const int t = threadIdx.x, lane = t & 31, wid = t >> 5;
    const int wy = wid >> 1, nx = wid & 1;
    const int n0 = blockIdx.x * 64, m0 = blockIdx.y * 128;

    const h16* A = g_cf + (size_t)m0 * 512;
    const h16* B = g_wof + (size_t)n0 * 512;

    float acc[2][4][4] = {};
    stage_cp<128, 256>(sb, A, 512, t);
    stage_cp<64, 256>(sb + B_OFF, B, 512, t);
    CP_COMMIT();
    for (int s = 0; s < 8; s++) {
        if (s + 1 < 8) {
            uint32_t nb = sb + ((s + 1) & 1) * BUFB;
            stage_cp<128, 256>(nb, A + (s + 1) * 64, 512, t);
            stage_cp<64, 256>(nb + B_OFF, B + (s + 1) * 64, 512, t);
            CP_COMMIT();
            CP_WAIT(1);
        } else {
            CP_WAIT(0);
        }
        __syncthreads();
        uint32_t buf = sb + (s & 1) * BUFB;
        compute_stage(buf + (uint32_t)(wy * 32) * STRB + lda_off(lane),
                      buf + B_OFF + (uint32_t)(nx * 32) * STRB + ldb_off(lane), acc);
        __syncthreads();
    }

    const int r = lane >> 2, cc = lane & 3;
    #pragma unroll
    for (int mi = 0; mi < 2; mi++)
    #pragma unroll
    for (int ni = 0; ni < 4; ni++)
    #pragma unroll
    for (int g = 0; g < 2; g++) {
        int m = m0 + wy * 32 + mi * 16 + r + g * 8;
        int n = n0 + nx * 32 + ni * 8 + cc * 2;
        float2 o;
        o.x = acc[mi][ni][2 * g]     + bo[n];
        o.y = acc[mi][ni][2 * g + 1] + bo[n + 1];
        *(float2*)&out[(size_t)m * 512 + n] = o;
    }
}

// ===========================================================================
extern "C" void kernel_launch(void* const* d_in, const int* in_sizes, int n_in,
                              void* d_out, int out_size) {
    const float* x   = (const float*)d_in[0];
    const float* Wq  = (const float*)d_in[1];
    const float* Wkv = (const float*)d_in[2];
    const float* Wo  = (const float*)d_in[3];
    const float* bo  = (const float*)d_in[4];
    const float* pos = (const float*)d_in[5];
    float* out = (float*)d_out;

    cudaFuncSetAttribute(mm_qkv,    cudaFuncAttributeMaxDynamicSharedMemorySize, SMEM_G);
    cudaFuncSetAttribute(mm_pos,    cudaFuncAttributeMaxDynamicSharedMemorySize, SMEM_POS);
    cudaFuncSetAttribute(fa_kernel, cudaFuncAttributeMaxDynamicSharedMemorySize, SMEM_FA);
    cudaFuncSetAttribute(mm_out,    cudaFuncAttributeMaxDynamicSharedMemorySize, SMEM_G);

    pack_x_kernel<<<4096, 256>>>(x);
    pack_w_kernel<<<1024, 256>>>(Wq, Wkv, Wo);
    pack_t_kernel<<<68, 256>>>(pos);

    mm_qkv   <<<dim3(24, 64), 256, SMEM_G>>>();
    mm_pos   <<<512,          256, SMEM_POS>>>();
    fa_kernel<<<dim3(8, 64),  256, SMEM_FA>>>();
    mm_out   <<<dim3(8, 64),  256, SMEM_G>>>(bo, out);
}

// round 16
// speedup vs baseline: 1.2478x; 1.0584x over previous
#include <cuda_runtime.h>
#include <cuda_fp16.h>
#include <cstdint>

#define Nn    1024
#define NPp   1025
#define NPS   1028
#define BHb   64
#define MXm   8192

typedef __half h16;

// ---------------- device scratch (all fp16) ----------------
__device__ h16 g_xf [(size_t)MXm * 512];
__device__ h16 g_wqf[(size_t)512 * 512];        // [n][k]
__device__ h16 g_wkvf[(size_t)1024 * 512];      // [n][k]
__device__ h16 g_wof[(size_t)512 * 512];        // [n][k]
__device__ h16 g_tf [(size_t)1088 * 64];        // pos table (padded)
__device__ h16 g_qf [(size_t)BHb * Nn * 64];    // scaled by 0.125*log2e
__device__ h16 g_kf [(size_t)BHb * Nn * 64];
__device__ h16 g_vtf[(size_t)BHb * 64 * Nn];    // v^T [bh][d][j]
__device__ h16 g_cf [(size_t)MXm * 512];        // ctx [b,n][h*d]
__device__ h16 g_Ph [(size_t)BHb * Nn * NPS];   // pos dots (scaled, exp2 domain)

// ---------------- smem geometry ----------------
#define STRB  144
#define B_OFF  18432u
#define BUFB   27648u
#define SMEM_G 55296
#define PB0      18432u
#define SMEM_POS 36864
#define FQ      0u
#define FKV0    18432u
#define FKVSTR  18432u
#define FK      0u
#define FV      9216u
#define SMEM_FA 55296

#define CP16(d, s)  asm volatile("cp.async.ca.shared.global [%0], [%1], 16;" :: "r"(d), "l"(s))
#define CP_COMMIT() asm volatile("cp.async.commit_group;" ::: "memory")
#define CP_WAIT(n)  asm volatile("cp.async.wait_group %0;" :: "n"(n) : "memory")

#define LDMX4(r0, r1, r2, r3, a) \
    asm volatile("ldmatrix.sync.aligned.m8n8.x4.shared.b16 {%0,%1,%2,%3}, [%4];" \
                 : "=r"(r0), "=r"(r1), "=r"(r2), "=r"(r3) : "r"(a))

static __device__ __forceinline__ uint32_t smem_u32(const void* p) {
    uint32_t a;
    asm("{ .reg .u64 t; cvta.to.shared.u64 t, %1; cvt.u32.u64 %0, t; }" : "=r"(a) : "l"(p));
    return a;
}
static __device__ __forceinline__ float ex2(float x) {
    float y;
    asm("ex2.approx.f32 %0, %1;" : "=f"(y) : "f"(x));
    return y;
}
static __device__ __forceinline__ void mma_f16(float* d, const uint32_t* a, const uint32_t* b) {
    asm volatile("mma.sync.aligned.m16n8k16.row.col.f32.f16.f16.f32 "
                 "{%0,%1,%2,%3}, {%4,%5,%6,%7}, {%8,%9}, {%0,%1,%2,%3};"
                 : "+f"(d[0]), "+f"(d[1]), "+f"(d[2]), "+f"(d[3])
                 : "r"(a[0]), "r"(a[1]), "r"(a[2]), "r"(a[3]), "r"(b[0]), "r"(b[1]));
}
static __device__ __forceinline__ uint32_t h2u(float a, float b) {
    __half2 h = __floats2half2_rn(a, b);
    return *(uint32_t*)&h;
}

template <int R, int T>
static __device__ __forceinline__ void stage_cp(uint32_t sdst, const h16* src, int lds, int t) {
    #pragma unroll
    for (int i = 0; i < R * 8 / T; i++) {
        int idx = t + i * T;
        int row = idx >> 3, ch = idx & 7;
        CP16(sdst + (uint32_t)row * STRB + (uint32_t)ch * 16,
             src + (size_t)row * lds + ch * 8);
    }
}

static __device__ __forceinline__ uint32_t lda_off(int lane) {
    return (uint32_t)(lane & 15) * STRB + (uint32_t)(lane & 16);
}
static __device__ __forceinline__ uint32_t ldb_off(int lane) {
    return (uint32_t)((lane & 7) + ((lane & 16) >> 1)) * STRB + (uint32_t)((lane & 8) << 1);
}

// single-term K=64 stage; warp tile 32x32
static __device__ __forceinline__ void compute_stage(uint32_t a_base, uint32_t b_base,
                                                     float acc[2][4][4]) {
    #pragma unroll
    for (int ks = 0; ks < 4; ks++) {
        uint32_t a[2][4], b[4][2];
        #pragma unroll
        for (int mi = 0; mi < 2; mi++) {
            uint32_t ad = a_base + (uint32_t)(mi * 16) * STRB + (uint32_t)(ks * 32);
            LDMX4(a[mi][0], a[mi][1], a[mi][2], a[mi][3], ad);
        }
        #pragma unroll
        for (int p = 0; p < 2; p++) {
            uint32_t bd = b_base + (uint32_t)(p * 16) * STRB + (uint32_t)(ks * 32);
            LDMX4(b[2 * p][0], b[2 * p][1], b[2 * p + 1][0], b[2 * p + 1][1], bd);
        }
        #pragma unroll
        for (int ni = 0; ni < 4; ni++)
            #pragma unroll
            for (int mi = 0; mi < 2; mi++)
                mma_f16(acc[mi][ni], a[mi], b[ni]);
    }
}

// ===========================================================================
// Prep kernels
// ===========================================================================
__global__ void pack_x_kernel(const float* __restrict__ x) {
    size_t e = ((size_t)blockIdx.x * 256 + threadIdx.x) * 4;
    float4 v = *(const float4*)(x + e);
    uint2 p;
    p.x = h2u(v.x, v.y);
    p.y = h2u(v.z, v.w);
    *(uint2*)&g_xf[e] = p;
}

__global__ void pack_w_kernel(const float* __restrict__ Wq, const float* __restrict__ Wkv,
                              const float* __restrict__ Wo) {
    size_t e0 = ((size_t)blockIdx.x * 256 + threadIdx.x) * 4;
    #pragma unroll
    for (int cc = 0; cc < 4; cc++) {
        size_t e = e0 + cc;
        if (e < 262144) {
            int k = (int)(e & 511), n = (int)(e >> 9);
            g_wqf[e] = __float2half(Wq[(size_t)k * 512 + n]);
        } else if (e < 786432) {
            size_t m = e - 262144;
            int k = (int)(m & 511), n = (int)(m >> 9);
            g_wkvf[m] = __float2half(Wkv[(size_t)k * 1024 + n]);
        } else {
            size_t m = e - 786432;
            int k = (int)(m & 511), n = (int)(m >> 9);
            g_wof[m] = __float2half(Wo[(size_t)k * 512 + n]);
        }
    }
}

__global__ void pack_t_kernel(const float* __restrict__ T) {
    size_t e0 = ((size_t)blockIdx.x * 256 + threadIdx.x) * 4;
    #pragma unroll
    for (int cc = 0; cc < 4; cc++) {
        size_t e = e0 + cc;
        int p = (int)(e >> 6), d = (int)(e & 63);
        g_tf[e] = __float2half((p < NPp) ? T[(size_t)p * 64 + d] : 0.f);
    }
}

// ===========================================================================
// GEMM 1: QKV.  q scaled by 0.125*log2(e).
// ===========================================================================
__global__ __launch_bounds__(256) void mm_qkv() {
    extern __shared__ uint8_t smem[];
    const uint32_t sb = smem_u32(smem);
    const int t = threadIdx.x, lane = t & 31, wid = t >> 5;
    const int wy = wid >> 1, nx = wid & 1;
    const int n0 = blockIdx.x * 64, m0 = blockIdx.y * 128;

    const h16* A = g_xf + (size_t)m0 * 512;
    const h16* B = (n0 < 512) ? (g_wqf + (size_t)n0 * 512) : (g_wkvf + (size_t)(n0 - 512) * 512);

    float acc[2][4][4] = {};
    stage_cp<128, 256>(sb, A, 512, t);
    stage_cp<64, 256>(sb + B_OFF, B, 512, t);
    CP_COMMIT();
    for (int s = 0; s < 8; s++) {
        if (s + 1 < 8) {
            uint32_t nb = sb + ((s + 1) & 1) * BUFB;
            stage_cp<128, 256>(nb, A + (s + 1) * 64, 512, t);
            stage_cp<64, 256>(nb + B_OFF, B + (s + 1) * 64, 512, t);
            CP_COMMIT();
            CP_WAIT(1);
        } else {
            CP_WAIT(0);
        }
        __syncthreads();
        uint32_t buf = sb + (s & 1) * BUFB;
        compute_stage(buf + (uint32_t)(wy * 32) * STRB + lda_off(lane),
                      buf + B_OFF + (uint32_t)(nx * 32) * STRB + ldb_off(lane), acc);
        __syncthreads();
    }

    const int b = m0 >> 10, i0 = m0 & 1023;
    const int region = n0 >> 9;
    const int h = (n0 >> 6) & 7;
    const int bh_idx = b * 8 + h;
    const int r = lane >> 2, cc = lane & 3;
    const float sc = (region == 0) ? 0.125f * 1.44269504f : 1.0f;

    if (region == 2) {
        #pragma unroll
        for (int mi = 0; mi < 2; mi++)
        #pragma unroll
        for (int ni = 0; ni < 4; ni++)
        #pragma unroll
        for (int g = 0; g < 2; g++) {
            int i = i0 + wy * 32 + mi * 16 + r + g * 8;
            int d = nx * 32 + ni * 8 + cc * 2;
            g_vtf[((size_t)bh_idx * 64 + d)     * 1024 + i] = __float2half(acc[mi][ni][2 * g]);
            g_vtf[((size_t)bh_idx * 64 + d + 1) * 1024 + i] = __float2half(acc[mi][ni][2 * g + 1]);
        }
    } else {
        h16* dst = (region == 0 ? g_qf : g_kf) + ((size_t)bh_idx * 1024 + i0) * 64;
        #pragma unroll
        for (int mi = 0; mi < 2; mi++)
        #pragma unroll
        for (int ni = 0; ni < 4; ni++)
        #pragma unroll
        for (int g = 0; g < 2; g++) {
            int il = wy * 32 + mi * 16 + r + g * 8;
            int d  = nx * 32 + ni * 8 + cc * 2;
            *(uint32_t*)&dst[(size_t)il * 64 + d] =
                h2u(sc * acc[mi][ni][2 * g], sc * acc[mi][ni][2 * g + 1]);
        }
    }
}

// ===========================================================================
// GEMM 2: P = q_scaled . T^T -> fp16.  grid(512), persistent A.
// ===========================================================================
__global__ __launch_bounds__(256) void mm_pos() {
    extern __shared__ uint8_t smem[];
    const uint32_t sb = smem_u32(smem);
    const int t = threadIdx.x, lane = t & 31, wid = t >> 5;
    const int wy = wid >> 1, nx = wid & 1;
    const int m0 = blockIdx.x * 128;
    const int r = lane >> 2, cc = lane & 3;

    stage_cp<128, 256>(sb, g_qf + (size_t)m0 * 64, 64, t);
    stage_cp<64, 256>(sb + PB0, g_tf, 64, t);
    CP_COMMIT();

    const uint32_t a_base = sb + (uint32_t)(wy * 32) * STRB + lda_off(lane);

    for (int pt = 0; pt < 17; pt++) {
        if (pt + 1 < 17) {
            stage_cp<64, 256>(sb + PB0 + ((pt + 1) & 1) * 9216u,
                              g_tf + (size_t)(pt + 1) * 64 * 64, 64, t);
            CP_COMMIT();
            CP_WAIT(1);
        } else {
            CP_WAIT(0);
        }
        __syncthreads();

        float acc[2][4][4] = {};
        uint32_t b_base = sb + PB0 + (uint32_t)(pt & 1) * 9216u
                        + (uint32_t)(nx * 32) * STRB + ldb_off(lane);
        compute_stage(a_base, b_base, acc);

        const int p0 = pt * 64;
        #pragma unroll
        for (int mi = 0; mi < 2; mi++)
        #pragma unroll
        for (int ni = 0; ni < 4; ni++)
        #pragma unroll
        for (int g = 0; g < 2; g++) {
            int m = m0 + wy * 32 + mi * 16 + r + g * 8;
            int p = p0 + nx * 32 + ni * 8 + cc * 2;
            if (p + 1 < NPp) {
                *(uint32_t*)&g_Ph[(size_t)m * NPS + p] =
                    h2u(acc[mi][ni][2 * g], acc[mi][ni][2 * g + 1]);
            } else if (p < NPp) {
                g_Ph[(size_t)m * NPS + p] = __float2half(acc[mi][ni][2 * g]);
            }
        }
        __syncthreads();
    }
}

// ===========================================================================
// Fused attention: grid(8, 64), 256 thr.  Warp owns 16 rows x all 64 j.
// Q fragments in registers (loaded once); P gather initializes the QK
// accumulator (loads issued before MMAs -> latency hidden).
// ===========================================================================
static __device__ __forceinline__ void fa_stage_kv(uint32_t kvb,
                                                   const h16* k, const h16* v, int j0, int t) {
    stage_cp<64, 256>(kvb + FK, k + (size_t)j0 * 64, 64, t);
    stage_cp<64, 256>(kvb + FV, v + j0, 1024, t);
    CP_COMMIT();
}

__global__ __launch_bounds__(256) void fa_kernel() {
    extern __shared__ uint8_t smem[];
    const uint32_t sb = smem_u32(smem);
    const int t = threadIdx.x, lane = t & 31, wid = t >> 5;
    const int r = lane >> 2, cc = lane & 3;
    const int i0 = blockIdx.x * 128, bh = blockIdx.y;

    const h16* q = g_qf + ((size_t)bh * 1024 + i0) * 64;
    const h16* k = g_kf + (size_t)bh * 1024 * 64;
    const h16* v = g_vtf + (size_t)bh * 64 * 1024;
    const h16* Pb = g_Ph + (size_t)bh * 1024 * NPS;

    stage_cp<128, 256>(sb + FQ, q, 64, t);
    fa_stage_kv(sb + FKV0, k, v, 0, t);

    const uint32_t q_base = sb + FQ + (uint32_t)(wid * 16) * STRB + lda_off(lane);
    const uint32_t k_rel  = FK + ldb_off(lane);
    const uint32_t v_rel  = FV + ldb_off(lane);

    // row indices and P row pointers for this thread (two row groups g=0,1)
    const int irow0 = i0 + wid * 16 + r;                  // g = 0
    const h16* prow0 = Pb + (size_t)irow0 * NPS + 512;
    const h16* prow1 = prow0 + (size_t)8 * NPS;           // g = 1 (row +8)

    float m_run[2] = {-1e30f, -1e30f};
    float l_run[2] = {0.f, 0.f};
    float oacc[8][4] = {};
    uint32_t qf[4][4];                                    // persistent Q fragments

    for (int jt = 0; jt < 16; jt++) {
        const uint32_t kvb = sb + FKV0 + (uint32_t)(jt & 1) * FKVSTR;
        if (jt + 1 < 16) {
            fa_stage_kv(sb + FKV0 + (uint32_t)((jt + 1) & 1) * FKVSTR, k, v, (jt + 1) * 64, t);
            CP_WAIT(1);
        } else {
            CP_WAIT(0);
        }
        __syncthreads();

        if (jt == 0) {
            #pragma unroll
            for (int ks = 0; ks < 4; ks++)
                LDMX4(qf[ks][0], qf[ks][1], qf[ks][2], qf[ks][3],
                      q_base + (uint32_t)(ks * 32));
        }

        // ---- init accumulator with positional term (gather BEFORE MMAs) ----
        const int j0 = jt * 64;
        float sacc[8][4];
        #pragma unroll
        for (int ni = 0; ni < 8; ni++) {
            int jb = j0 + ni * 8 + cc * 2;
            int d00 = max(-512, min(512, irow0 - jb));
            int d01 = max(-512, min(512, irow0 - jb - 1));
            int d10 = max(-512, min(512, irow0 + 8 - jb));
            int d11 = max(-512, min(512, irow0 + 8 - jb - 1));
            sacc[ni][0] = __half2float(__ldg(prow0 + d00));
            sacc[ni][1] = __half2float(__ldg(prow0 + d01));
            sacc[ni][2] = __half2float(__ldg(prow1 + d10));
            sacc[ni][3] = __half2float(__ldg(prow1 + d11));
        }

        // ---- QK^T accumulate on top of P ----
        #pragma unroll
        for (int ks = 0; ks < 4; ks++) {
            uint32_t kb[8][2];
            #pragma unroll
            for (int p3 = 0; p3 < 4; p3++) {
                uint32_t bd = kvb + k_rel + (uint32_t)(p3 * 16) * STRB + (uint32_t)(ks * 32);
                LDMX4(kb[2 * p3][0], kb[2 * p3][1], kb[2 * p3 + 1][0], kb[2 * p3 + 1][1], bd);
            }
            #pragma unroll
            for (int ni = 0; ni < 8; ni++)
                mma_f16(sacc[ni], qf[ks], kb[ni]);
        }

        // ---- warp-local online softmax (exp2 domain) ----
        float mnew[2], f[2];
        #pragma unroll
        for (int g = 0; g < 2; g++) {
            float m = fmaxf(sacc[0][2 * g], sacc[0][2 * g + 1]);
            #pragma unroll
            for (int ni = 1; ni < 8; ni++)
                m = fmaxf(m, fmaxf(sacc[ni][2 * g], sacc[ni][2 * g + 1]));
            m = fmaxf(m, __shfl_xor_sync(0xffffffffu, m, 1));
            m = fmaxf(m, __shfl_xor_sync(0xffffffffu, m, 2));
            float mn = fmaxf(m_run[g], m);
            f[g] = ex2(m_run[g] - mn);
            m_run[g] = mn;
            mnew[g] = mn;
        }
        #pragma unroll
        for (int ni = 0; ni < 8; ni++)
            #pragma unroll
            for (int e = 0; e < 4; e++)
                sacc[ni][e] = ex2(sacc[ni][e] - mnew[e >> 1]);
        #pragma unroll
        for (int g = 0; g < 2; g++) {
            float s = 0.f;
            #pragma unroll
            for (int ni = 0; ni < 8; ni++)
                s += sacc[ni][2 * g] + sacc[ni][2 * g + 1];
            s += __shfl_xor_sync(0xffffffffu, s, 1);
            s += __shfl_xor_sync(0xffffffffu, s, 2);
            l_run[g] = l_run[g] * f[g] + s;
        }
        #pragma unroll
        for (int dn = 0; dn < 8; dn++)
            #pragma unroll
            for (int e = 0; e < 4; e++)
                oacc[dn][e] *= f[e >> 1];

        // ---- SV: p fragments via C->A identity; B = V^T ----
        #pragma unroll
        for (int c = 0; c < 4; c++) {
            uint32_t vb[8][2];
            #pragma unroll
            for (int p3 = 0; p3 < 4; p3++) {
                uint32_t vd = kvb + v_rel + (uint32_t)(p3 * 16) * STRB + (uint32_t)(c * 32);
                LDMX4(vb[2 * p3][0], vb[2 * p3][1], vb[2 * p3 + 1][0], vb[2 * p3 + 1][1], vd);
            }
            uint32_t pa[4];
            pa[0] = h2u(sacc[2 * c][0],     sacc[2 * c][1]);
            pa[1] = h2u(sacc[2 * c][2],     sacc[2 * c][3]);
            pa[2] = h2u(sacc[2 * c + 1][0], sacc[2 * c + 1][1]);
            pa[3] = h2u(sacc[2 * c + 1][2], sacc[2 * c + 1][3]);
            #pragma unroll
            for (int dn = 0; dn < 8; dn++)
                mma_f16(oacc[dn], pa, vb[dn]);
        }
        __syncthreads();
    }

    // ---- epilogue: O /= l, write ctx fp16 ----
    const int b = bh >> 3, hh = bh & 7;
    float inv[2] = {1.0f / l_run[0], 1.0f / l_run[1]};
    #pragma unroll
    for (int dn = 0; dn < 8; dn++)
    #pragma unroll
    for (int g = 0; g < 2; g++) {
        int gi = i0 + wid * 16 + g * 8 + r;
        int d  = dn * 8 + cc * 2;
        size_t off = ((size_t)(b * 1024 + gi)) * 512 + hh * 64 + d;
        *(uint32_t*)&g_cf[off] = h2u(oacc[dn][2 * g] * inv[g], oacc[dn][2 * g + 1] * inv[g]);
    }
}

// ===========================================================================
// GEMM 5: out = ctx @ Wo + bo.  grid(8, 64), 256 thr.
// ===========================================================================
__global__ __launch_bounds__(256) void mm_out(const float* __restrict__ bo,
                                              float* __restrict__ out) {
    extern __shared__ uint8_t smem[];
    const uint32_t sb = smem_u32(smem);
    const int t = threadIdx.x, lane = t & 31, wid = t >> 5;
    const int wy = wid >> 1, nx = wid & 1;
    const int n0 = blockIdx.x * 64, m0 = blockIdx.y * 128;

    const h16* A = g_cf + (size_t)m0 * 512;
    const h16* B = g_wof + (size_t)n0 * 512;

    float acc[2][4][4] = {};
    stage_cp<128, 256>(sb, A, 512, t);
    stage_cp<64, 256>(sb + B_OFF, B, 512, t);
    CP_COMMIT();
    for (int s = 0; s < 8; s++) {
        if (s + 1 < 8) {
            uint32_t nb = sb + ((s + 1) & 1) * BUFB;
            stage_cp<128, 256>(nb, A + (s + 1) * 64, 512, t);
            stage_cp<64, 256>(nb + B_OFF, B + (s + 1) * 64, 512, t);
            CP_COMMIT();
            CP_WAIT(1);
        } else {
            CP_WAIT(0);
        }
        __syncthreads();
        uint32_t buf = sb + (s & 1) * BUFB;
        compute_stage(buf + (uint32_t)(wy * 32) * STRB + lda_off(lane),
                      buf + B_OFF + (uint32_t)(nx * 32) * STRB + ldb_off(lane), acc);
        __syncthreads();
    }

    const int r = lane >> 2, cc = lane & 3;
    #pragma unroll
    for (int mi = 0; mi < 2; mi++)
    #pragma unroll
    for (int ni = 0; ni < 4; ni++)
    #pragma unroll
    for (int g = 0; g < 2; g++) {
        int m = m0 + wy * 32 + mi * 16 + r + g * 8;
        int n = n0 + nx * 32 + ni * 8 + cc * 2;
        float2 o;
        o.x = acc[mi][ni][2 * g]     + bo[n];
        o.y = acc[mi][ni][2 * g + 1] + bo[n + 1];
        *(float2*)&out[(size_t)m * 512 + n] = o;
    }
}

// ===========================================================================
extern "C" void kernel_launch(void* const* d_in, const int* in_sizes, int n_in,
                              void* d_out, int out_size) {
    const float* x   = (const float*)d_in[0];
    const float* Wq  = (const float*)d_in[1];
    const float* Wkv = (const float*)d_in[2];
    const float* Wo  = (const float*)d_in[3];
    const float* bo  = (const float*)d_in[4];
    const float* pos = (const float*)d_in[5];
    float* out = (float*)d_out;

    cudaFuncSetAttribute(mm_qkv,    cudaFuncAttributeMaxDynamicSharedMemorySize, SMEM_G);
    cudaFuncSetAttribute(mm_pos,    cudaFuncAttributeMaxDynamicSharedMemorySize, SMEM_POS);
    cudaFuncSetAttribute(fa_kernel, cudaFuncAttributeMaxDynamicSharedMemorySize, SMEM_FA);
    cudaFuncSetAttribute(mm_out,    cudaFuncAttributeMaxDynamicSharedMemorySize, SMEM_G);

    pack_x_kernel<<<4096, 256>>>(x);
    pack_w_kernel<<<1024, 256>>>(Wq, Wkv, Wo);
    pack_t_kernel<<<68, 256>>>(pos);

    mm_qkv   <<<dim3(24, 64), 256, SMEM_G>>>();
    mm_pos   <<<512,          256, SMEM_POS>>>();
    fa_kernel<<<dim3(8, 64),  256, SMEM_FA>>>();
    mm_out   <<<dim3(8, 64),  256, SMEM_G>>>(bo, out);
}